// round 1
// baseline (speedup 1.0000x reference)
#include <cuda_runtime.h>
#include <cuda_bf16.h>

// out[row, i, e] = x[row, i] * W[i, e] + b[i, e]
// rows = 16384, i in [0,200), e in [0,64)
// Store-bound: 839 MB output. Strategy: cache W+bias (102.4 KB) in smem once
// per block, emit RPB rows per block to amortize the W/bias L2 traffic.

#define N_NUM   200
#define EMB     64
#define N_ROWS  16384
#define E4      (EMB / 4)           // 16 float4 per feature
#define PAIRS   (N_NUM * E4)        // 3200 float4 per row
#define RPB     8                   // rows per block
#define NTHREADS 256
#define NBLOCKS (N_ROWS / RPB)      // 2048

// dynamic smem layout: [ sW: PAIRS float4 | sB: PAIRS float4 | sx: RPB*N_NUM float ]
#define SMEM_BYTES (2 * PAIRS * (int)sizeof(float4) + RPB * N_NUM * (int)sizeof(float))

__global__ __launch_bounds__(NTHREADS, 2)
void numproj_kernel(const float* __restrict__ x,
                    const float4* __restrict__ W4,
                    const float4* __restrict__ B4,
                    float4* __restrict__ out)
{
    extern __shared__ float4 smem[];
    float4* sW = smem;                       // PAIRS
    float4* sB = smem + PAIRS;               // PAIRS
    float*  sx = (float*)(smem + 2 * PAIRS); // RPB * N_NUM

    const int tid  = threadIdx.x;
    const int row0 = blockIdx.x * RPB;

    // Stage W and bias (read once per block -> 210 MB total L2 traffic vs 1.68 GB naive)
    #pragma unroll
    for (int j = tid; j < PAIRS; j += NTHREADS) {
        sW[j] = W4[j];
        sB[j] = B4[j];
    }
    // Stage the RPB x-rows this block will broadcast
    for (int j = tid; j < RPB * N_NUM; j += NTHREADS) {
        sx[j] = x[row0 * N_NUM + j];
    }
    __syncthreads();

    // Emit RPB rows; consecutive threads write consecutive float4 -> fully
    // coalesced STG.128. sx read is a 16-thread broadcast (conflict-free).
    for (int r = 0; r < RPB; ++r) {
        float4* __restrict__ orow = out + (size_t)(row0 + r) * PAIRS;
        const float* xr = sx + r * N_NUM;
        #pragma unroll 1
        for (int j = tid; j < PAIRS; j += NTHREADS) {
            const float  xv = xr[j >> 4];
            const float4 w  = sW[j];
            const float4 b  = sB[j];
            float4 o;
            o.x = fmaf(xv, w.x, b.x);
            o.y = fmaf(xv, w.y, b.y);
            o.z = fmaf(xv, w.z, b.z);
            o.w = fmaf(xv, w.w, b.w);
            orow[j] = o;
        }
    }
}

extern "C" void kernel_launch(void* const* d_in, const int* in_sizes, int n_in,
                              void* d_out, int out_size)
{
    const float*  x  = (const float*) d_in[0];   // [16384, 200] f32
    const float4* W4 = (const float4*)d_in[1];   // [200, 64]  f32 -> [3200] float4
    const float4* B4 = (const float4*)d_in[2];   // [200, 64]  f32 -> [3200] float4
    float4* out = (float4*)d_out;

    // Opt in to >48KB dynamic smem (host-side attr set; not a stream op, capture-safe)
    cudaFuncSetAttribute(numproj_kernel,
                         cudaFuncAttributeMaxDynamicSharedMemorySize, SMEM_BYTES);

    numproj_kernel<<<NBLOCKS, NTHREADS, SMEM_BYTES>>>(x, W4, B4, out);
}

// round 2
// speedup vs baseline: 1.0547x; 1.0547x over previous
#include <cuda_runtime.h>
#include <cuda_bf16.h>

// out[row, i, e] = x[row, i] * W[i, e] + b[i, e]
// rows = 16384, i in [0,200), e in [0,64)  -> 3200 float4 columns per row.
//
// Round-2 strategy: thread-per-column, W/b in REGISTERS (loaded once),
// loop over rows. No smem, no syncs, minimal L1 traffic (store stream only
// + warp-broadcast x loads). Pure streaming-store kernel.

#define N_NUM    200
#define E4       16                  // float4 per feature
#define COLS     (N_NUM * E4)        // 3200 float4 per row
#define N_ROWS   16384
#define TPB      128                 // threads per block (columns per block)
#define CBLKS    (COLS / TPB)        // 25 column blocks
#define RPB      128                 // rows per block
#define RBLKS    (N_ROWS / RPB)      // 128 row blocks
#define RUNROLL  4

__global__ __launch_bounds__(TPB)
void numproj_kernel(const float* __restrict__ x,
                    const float4* __restrict__ W4,
                    const float4* __restrict__ B4,
                    float4* __restrict__ out)
{
    const int j    = blockIdx.x * TPB + threadIdx.x;   // column 0..3199
    const int i    = j >> 4;                            // feature 0..199
    const int row0 = blockIdx.y * RPB;

    // Per-thread constants for this column, held in registers for all rows.
    const float4 w = __ldg(&W4[j]);
    const float4 b = __ldg(&B4[j]);

    const float*  xp = x + (size_t)row0 * N_NUM + i;    // step N_NUM per row
    float4*       op = out + (size_t)row0 * COLS + j;   // step COLS per row

    #pragma unroll 1
    for (int r = 0; r < RPB; r += RUNROLL) {
        // Batch x loads first for MLP (warp sees 2 distinct addresses per row).
        float xv[RUNROLL];
        #pragma unroll
        for (int u = 0; u < RUNROLL; ++u)
            xv[u] = __ldg(xp + (size_t)u * N_NUM);

        #pragma unroll
        for (int u = 0; u < RUNROLL; ++u) {
            float4 o;
            o.x = fmaf(xv[u], w.x, b.x);
            o.y = fmaf(xv[u], w.y, b.y);
            o.z = fmaf(xv[u], w.z, b.z);
            o.w = fmaf(xv[u], w.w, b.w);
            __stcs(op + (size_t)u * COLS, o);   // streaming store: don't pollute L2
        }
        xp += (size_t)RUNROLL * N_NUM;
        op += (size_t)RUNROLL * COLS;
    }
}

extern "C" void kernel_launch(void* const* d_in, const int* in_sizes, int n_in,
                              void* d_out, int out_size)
{
    const float*  x  = (const float*) d_in[0];   // [16384, 200] f32
    const float4* W4 = (const float4*)d_in[1];   // [200, 64] f32 -> 3200 float4
    const float4* B4 = (const float4*)d_in[2];
    float4* out = (float4*)d_out;

    dim3 grid(CBLKS, RBLKS);   // 25 x 128 = 3200 blocks
    numproj_kernel<<<grid, TPB>>>(x, W4, B4, out);
}

// round 4
// speedup vs baseline: 1.0652x; 1.0100x over previous
#include <cuda_runtime.h>
#include <cuda_bf16.h>
#include <cstdint>

// out[row, i, e] = x[row, i] * W[i, e] + b[i, e]
// rows = 16384, i in [0,200), e in [0,64).
//
// Round-3: 256-bit streaming stores (STG.E.256, sm_100+), thread-per-32B
// output chunk with W/b in registers, short blocks for wave balance.

#define N_NUM    200
#define E4       16                   // float4 per feature
#define COLS     (N_NUM * E4)         // 3200 float4 per row
#define CHUNKS   (COLS / 2)           // 1600 32B-chunks per row
#define N_ROWS   16384
#define TPB      64                   // threads per block -> 64 chunks (2KB) per block
#define CBLKS    (CHUNKS / TPB)       // 25 column blocks
#define RPB      32                   // rows per block (short blocks, small tail)
#define RBLKS    (N_ROWS / RPB)       // 512 row blocks
#define RUNROLL  4

__device__ __forceinline__ void stg256_cs(void* p,
                                          float4 a, float4 b)
{
    asm volatile(
        "st.global.cs.v8.b32 [%0], {%1,%2,%3,%4,%5,%6,%7,%8};"
        :: "l"(p),
           "r"(__float_as_uint(a.x)), "r"(__float_as_uint(a.y)),
           "r"(__float_as_uint(a.z)), "r"(__float_as_uint(a.w)),
           "r"(__float_as_uint(b.x)), "r"(__float_as_uint(b.y)),
           "r"(__float_as_uint(b.z)), "r"(__float_as_uint(b.w))
        : "memory");
}

__global__ __launch_bounds__(TPB)
void numproj_kernel(const float* __restrict__ x,
                    const float4* __restrict__ W4,
                    const float4* __restrict__ B4,
                    float4* __restrict__ out)
{
    const int c    = blockIdx.x * TPB + threadIdx.x;  // 32B chunk 0..1599
    const int j0   = 2 * c;                           // first float4 column
    const int i    = c >> 3;                          // feature 0..199
    const int row0 = blockIdx.y * RPB;

    // Per-column constants held in registers for all rows.
    const float4 w0 = __ldg(&W4[j0]);
    const float4 w1 = __ldg(&W4[j0 + 1]);
    const float4 b0 = __ldg(&B4[j0]);
    const float4 b1 = __ldg(&B4[j0 + 1]);

    const float* xp = x + (size_t)row0 * N_NUM + i;
    char* op = (char*)(out + (size_t)row0 * COLS + j0);
    const size_t row_bytes = (size_t)COLS * sizeof(float4);

    #pragma unroll 1
    for (int r = 0; r < RPB; r += RUNROLL) {
        float xv[RUNROLL];
        #pragma unroll
        for (int u = 0; u < RUNROLL; ++u)
            xv[u] = __ldg(xp + (size_t)u * N_NUM);

        #pragma unroll
        for (int u = 0; u < RUNROLL; ++u) {
            float4 o0, o1;
            o0.x = fmaf(xv[u], w0.x, b0.x);
            o0.y = fmaf(xv[u], w0.y, b0.y);
            o0.z = fmaf(xv[u], w0.z, b0.z);
            o0.w = fmaf(xv[u], w0.w, b0.w);
            o1.x = fmaf(xv[u], w1.x, b1.x);
            o1.y = fmaf(xv[u], w1.y, b1.y);
            o1.z = fmaf(xv[u], w1.z, b1.z);
            o1.w = fmaf(xv[u], w1.w, b1.w);
            stg256_cs(op + (size_t)u * row_bytes, o0, o1);
        }
        xp += (size_t)RUNROLL * N_NUM;
        op += (size_t)RUNROLL * row_bytes;
    }
}

extern "C" void kernel_launch(void* const* d_in, const int* in_sizes, int n_in,
                              void* d_out, int out_size)
{
    const float*  x  = (const float*) d_in[0];   // [16384, 200] f32
    const float4* W4 = (const float4*)d_in[1];   // [200, 64] f32 -> 3200 float4
    const float4* B4 = (const float4*)d_in[2];
    float4* out = (float4*)d_out;

    dim3 grid(CBLKS, RBLKS);   // 25 x 512 = 12800 short blocks
    numproj_kernel<<<grid, TPB>>>(x, W4, B4, out);
}

// round 5
// speedup vs baseline: 1.0753x; 1.0094x over previous
#include <cuda_runtime.h>
#include <cuda_bf16.h>
#include <cstdint>

// out[row, i, e] = x[row, i] * W[i, e] + b[i, e]
// rows = 16384, i in [0,200), e in [0,64).
//
// Round-4: as round-3 (STG.E.256 streaming stores, W/b register-resident,
// thread-per-32B chunk) but: force 32 regs so all 32 CTAs/SM fit in the RF
// (occ 69.5% -> ~100%, more store wavefronts in flight), and halve rows-per
// -block for a smaller tail.

#define N_NUM    200
#define E4       16                   // float4 per feature
#define COLS     (N_NUM * E4)         // 3200 float4 per row
#define CHUNKS   (COLS / 2)           // 1600 32B-chunks per row
#define N_ROWS   16384
#define TPB      64
#define CBLKS    (CHUNKS / TPB)       // 25 column blocks
#define RPB      16                   // rows per block
#define RBLKS    (N_ROWS / RPB)       // 1024 row blocks
#define RUNROLL  4

__device__ __forceinline__ void stg256_cs(void* p, float4 a, float4 b)
{
    asm volatile(
        "st.global.cs.v8.b32 [%0], {%1,%2,%3,%4,%5,%6,%7,%8};"
        :: "l"(p),
           "r"(__float_as_uint(a.x)), "r"(__float_as_uint(a.y)),
           "r"(__float_as_uint(a.z)), "r"(__float_as_uint(a.w)),
           "r"(__float_as_uint(b.x)), "r"(__float_as_uint(b.y)),
           "r"(__float_as_uint(b.z)), "r"(__float_as_uint(b.w))
        : "memory");
}

__global__ __launch_bounds__(TPB, 32)   // force regs<=32: full 2048 thr/SM
void numproj_kernel(const float* __restrict__ x,
                    const float4* __restrict__ W4,
                    const float4* __restrict__ B4,
                    float4* __restrict__ out)
{
    const int c    = blockIdx.x * TPB + threadIdx.x;  // 32B chunk 0..1599
    const int j0   = 2 * c;                           // first float4 column
    const int i    = c >> 3;                          // feature 0..199
    const int row0 = blockIdx.y * RPB;

    // Per-column constants held in registers for all rows.
    const float4 w0 = __ldg(&W4[j0]);
    const float4 w1 = __ldg(&W4[j0 + 1]);
    const float4 b0 = __ldg(&B4[j0]);
    const float4 b1 = __ldg(&B4[j0 + 1]);

    const float* xp = x + (size_t)row0 * N_NUM + i;
    char* op = (char*)(out + (size_t)row0 * COLS + j0);
    const size_t row_bytes = (size_t)COLS * sizeof(float4);

    #pragma unroll 1
    for (int r = 0; r < RPB; r += RUNROLL) {
        float xv[RUNROLL];
        #pragma unroll
        for (int u = 0; u < RUNROLL; ++u)
            xv[u] = __ldg(xp + (size_t)u * N_NUM);

        #pragma unroll
        for (int u = 0; u < RUNROLL; ++u) {
            float4 o0, o1;
            o0.x = fmaf(xv[u], w0.x, b0.x);
            o0.y = fmaf(xv[u], w0.y, b0.y);
            o0.z = fmaf(xv[u], w0.z, b0.z);
            o0.w = fmaf(xv[u], w0.w, b0.w);
            o1.x = fmaf(xv[u], w1.x, b1.x);
            o1.y = fmaf(xv[u], w1.y, b1.y);
            o1.z = fmaf(xv[u], w1.z, b1.z);
            o1.w = fmaf(xv[u], w1.w, b1.w);
            stg256_cs(op + (size_t)u * row_bytes, o0, o1);
        }
        xp += (size_t)RUNROLL * N_NUM;
        op += (size_t)RUNROLL * row_bytes;
    }
}

extern "C" void kernel_launch(void* const* d_in, const int* in_sizes, int n_in,
                              void* d_out, int out_size)
{
    const float*  x  = (const float*) d_in[0];   // [16384, 200] f32
    const float4* W4 = (const float4*)d_in[1];   // [200, 64] f32 -> 3200 float4
    const float4* B4 = (const float4*)d_in[2];
    float4* out = (float4*)d_out;

    dim3 grid(CBLKS, RBLKS);   // 25 x 1024 = 25600 short blocks
    numproj_kernel<<<grid, TPB>>>(x, W4, B4, out);
}